// round 8
// baseline (speedup 1.0000x reference)
#include <cuda_runtime.h>

// 3-layer LSTM (IN=5, H=50) + FC(50->1), B=1024, T=512.
// v7: layer-pipelined warp specialization, BALANCED stages.
//   L1 group (100 thr, tid 0-99)    layer1 @ t = ph   (2-way K-split)
//   L2 group (200 thr, tid 100-299) layer2 @ t = ph-1 (4-way K-split)
//   L3 group (200 thr, tid 300-499) layer3 @ t = ph-2 (4-way K-split)
//   spares   (tid 500-511)          prefetch x(ph+1)  (3 slots each)
// One __syncthreads per phase (514 phases). Every gate thread now does
// ~77 LDS.128 + ~390 FFMA2 per phase (v6's L1 did 2x that and was the
// pipeline straggler). All shfl groups pair/quad lane-aligned; masks are
// minimal per-pair/per-quad. No dynamic register indexing anywhere.

#define T_STEPS   512
#define IN_DIM    5
#define HID       50
#define NB        7
#define NTHREADS  512
#define GRID      148
#define WSTR      808          // floats per kq block (200 rows * 4 + 8 pad)

// smem offsets (floats)
enum {
    W1_OFF = 0,                 // 14 * 808 = 11312
    W2_OFF = 11312,             // 25 * 808 = 20200
    W3_OFF = 31512,             // 20200
    V1_OFF = 51712,             // 2 bufs * 7 * 60   [x(5),pad,h1(50),pad4]
    V2_OFF = 52552,             // 2 bufs * 7 * 108  [h1(50),h2(50),pad8]
    V3_OFF = 54064,             // 2 bufs * 7 * 108  [h2(50),h3(50),pad8]
    SH_FLOATS = 55576           // 222304 bytes
};
#define V1S 60
#define V2S 108
#define V1B (NB * V1S)          // 420
#define V2B (NB * V2S)          // 756

typedef unsigned long long ull;

__device__ __forceinline__ ull ffma2(ull a, ull b, ull c) {
    ull d;
    asm("fma.rn.f32x2 %0, %1, %2, %3;" : "=l"(d) : "l"(a), "l"(b), "l"(c));
    return d;
}
__device__ __forceinline__ float fast_ex2(float x) {
    float y; asm("ex2.approx.ftz.f32 %0, %1;" : "=f"(y) : "f"(x)); return y;
}
__device__ __forceinline__ float fast_rcp(float x) {
    float y; asm("rcp.approx.ftz.f32 %0, %1;" : "=f"(y) : "f"(x)); return y;
}
__device__ __forceinline__ float sigm(float x) {
    return fast_rcp(1.0f + fast_ex2(-1.4426950408889634f * x));
}
__device__ __forceinline__ float tanh_acc(float x) {
    float r = fast_rcp(1.0f + fast_ex2(-2.8853900817779268f * x));
    return r + r - 1.0f;
}
__device__ __forceinline__ float lohi(ull a) {
    float lo, hi;
    asm("mov.b64 {%0, %1}, %2;" : "=f"(lo), "=f"(hi) : "l"(a));
    return lo + hi;
}
__device__ __forceinline__ float pick4(float a0, float a1, float a2, float a3,
                                       int k) {
    float x = (k & 1) ? a1 : a0;
    float y = (k & 1) ? a3 : a2;
    return (k & 2) ? y : x;
}

// ---- Layer 1: 100 threads, 2-way K-split over 14 kq blocks ----
__device__ __forceinline__ void layer1_phase(float* sh, int p, int q, int j,
                                             int ks, unsigned pmask,
                                             const float bz[4], float c1[4]) {
    ull acc[4][NB];
#pragma unroll
    for (int g = 0; g < 4; g++)
#pragma unroll
        for (int b = 0; b < NB; b++) acc[g][b] = 0ull;

    const float* vb = sh + V1_OFF + p * V1B;
#pragma unroll
    for (int i = 0; i < 7; i++) {
        const int kq0 = 2 * i;   // + ks at runtime
        const ulonglong2* wq = reinterpret_cast<const ulonglong2*>(
            sh + W1_OFF + (ks + kq0) * WSTR);
        ulonglong2 w0 = wq[j];
        ulonglong2 w1 = wq[j + HID];
        ulonglong2 w2 = wq[j + 2 * HID];
        ulonglong2 w3 = wq[j + 3 * HID];
#pragma unroll
        for (int b = 0; b < NB; b++) {
            ulonglong2 v = *reinterpret_cast<const ulonglong2*>(
                vb + b * V1S + (ks + kq0) * 4);
            acc[0][b] = ffma2(w0.x, v.x, acc[0][b]);
            acc[0][b] = ffma2(w0.y, v.y, acc[0][b]);
            acc[1][b] = ffma2(w1.x, v.x, acc[1][b]);
            acc[1][b] = ffma2(w1.y, v.y, acc[1][b]);
            acc[2][b] = ffma2(w2.x, v.x, acc[2][b]);
            acc[2][b] = ffma2(w2.y, v.y, acc[2][b]);
            acc[3][b] = ffma2(w3.x, v.x, acc[3][b]);
            acc[3][b] = ffma2(w3.y, v.y, acc[3][b]);
        }
    }
    float s[4][NB];
#pragma unroll
    for (int g = 0; g < 4; g++)
#pragma unroll
        for (int b = 0; b < NB; b++) {
            float v = lohi(acc[g][b]);
            v += __shfl_xor_sync(pmask, v, 1);
            s[g][b] = v;
        }
    // ks=0 updates batches 0-3 (c1[0..3]); ks=1 updates 4-6 (c1[0..2])
    if (ks == 0) {
#pragma unroll
        for (int b = 0; b < 4; b++) {
            float iv = sigm(s[0][b] + bz[0]);
            float fv = sigm(s[1][b] + bz[1]);
            float gv = tanh_acc(s[2][b] + bz[2]);
            float ov = sigm(s[3][b] + bz[3]);
            c1[b] = fv * c1[b] + iv * gv;
            float h = ov * tanh_acc(c1[b]);
            sh[V1_OFF + q * V1B + b * V1S + 6 + j] = h;
            sh[V2_OFF + q * V2B + b * V2S + j]     = h;
        }
    } else {
#pragma unroll
        for (int b = 0; b < 3; b++) {
            const int bb = b + 4;
            float iv = sigm(s[0][bb] + bz[0]);
            float fv = sigm(s[1][bb] + bz[1]);
            float gv = tanh_acc(s[2][bb] + bz[2]);
            float ov = sigm(s[3][bb] + bz[3]);
            c1[b] = fv * c1[b] + iv * gv;
            float h = ov * tanh_acc(c1[b]);
            sh[V1_OFF + q * V1B + bb * V1S + 6 + j] = h;
            sh[V2_OFF + q * V2B + bb * V2S + j]     = h;
        }
    }
}

// ---- Layers 2/3: 200 threads, 4-way K-split over KQ=25 ----
template<bool HAS2>
__device__ __forceinline__ void layer_hid_phase(float* sh,
                                                const float* __restrict__ shw,
                                                const float* __restrict__ vrd,
                                                int j, int ks, unsigned qmask,
                                                const float bz[4],
                                                float& ca, float& cb,
                                                int wr1, int wr2) {
    ull acc[4][NB];
#pragma unroll
    for (int g = 0; g < 4; g++)
#pragma unroll
        for (int b = 0; b < NB; b++) acc[g][b] = 0ull;

#pragma unroll
    for (int i = 0; i < 6; i++) {
        const int kq0 = 4 * i;
        const ulonglong2* wq = reinterpret_cast<const ulonglong2*>(
            shw + (ks + kq0) * WSTR);
        ulonglong2 w0 = wq[j];
        ulonglong2 w1 = wq[j + HID];
        ulonglong2 w2 = wq[j + 2 * HID];
        ulonglong2 w3 = wq[j + 3 * HID];
#pragma unroll
        for (int b = 0; b < NB; b++) {
            ulonglong2 v = *reinterpret_cast<const ulonglong2*>(
                vrd + b * V2S + (ks + kq0) * 4);
            acc[0][b] = ffma2(w0.x, v.x, acc[0][b]);
            acc[0][b] = ffma2(w0.y, v.y, acc[0][b]);
            acc[1][b] = ffma2(w1.x, v.x, acc[1][b]);
            acc[1][b] = ffma2(w1.y, v.y, acc[1][b]);
            acc[2][b] = ffma2(w2.x, v.x, acc[2][b]);
            acc[2][b] = ffma2(w2.y, v.y, acc[2][b]);
            acc[3][b] = ffma2(w3.x, v.x, acc[3][b]);
            acc[3][b] = ffma2(w3.y, v.y, acc[3][b]);
        }
    }
    if (ks == 0) {   // tail kq = 24
        const ulonglong2* wq = reinterpret_cast<const ulonglong2*>(
            shw + 24 * WSTR);
        ulonglong2 w0 = wq[j];
        ulonglong2 w1 = wq[j + HID];
        ulonglong2 w2 = wq[j + 2 * HID];
        ulonglong2 w3 = wq[j + 3 * HID];
#pragma unroll
        for (int b = 0; b < NB; b++) {
            ulonglong2 v = *reinterpret_cast<const ulonglong2*>(
                vrd + b * V2S + 24 * 4);
            acc[0][b] = ffma2(w0.x, v.x, acc[0][b]);
            acc[0][b] = ffma2(w0.y, v.y, acc[0][b]);
            acc[1][b] = ffma2(w1.x, v.x, acc[1][b]);
            acc[1][b] = ffma2(w1.y, v.y, acc[1][b]);
            acc[2][b] = ffma2(w2.x, v.x, acc[2][b]);
            acc[2][b] = ffma2(w2.y, v.y, acc[2][b]);
            acc[3][b] = ffma2(w3.x, v.x, acc[3][b]);
            acc[3][b] = ffma2(w3.y, v.y, acc[3][b]);
        }
    }

    float s[4][NB];
#pragma unroll
    for (int g = 0; g < 4; g++)
#pragma unroll
        for (int b = 0; b < NB; b++) {
            float v = lohi(acc[g][b]);
            v += __shfl_xor_sync(qmask, v, 1);
            v += __shfl_xor_sync(qmask, v, 2);
            s[g][b] = v;
        }

    float t0[4], t1[4];
#pragma unroll
    for (int g = 0; g < 4; g++) {
        t0[g] = pick4(s[g][0], s[g][2], s[g][4], s[g][6], ks) + bz[g];
        t1[g] = pick4(s[g][1], s[g][3], s[g][5], s[g][5], ks) + bz[g];
    }
    const int b0 = 2 * ks;
    {
        float iv = sigm(t0[0]);
        float fv = sigm(t0[1]);
        float gv = tanh_acc(t0[2]);
        float ov = sigm(t0[3]);
        ca = fv * ca + iv * gv;
        float h = ov * tanh_acc(ca);
        sh[wr1 + b0 * V2S] = h;
        if (HAS2) sh[wr2 + b0 * V2S] = h;
    }
    if (ks < 3) {
        const int b1 = 2 * ks + 1;
        float iv = sigm(t1[0]);
        float fv = sigm(t1[1]);
        float gv = tanh_acc(t1[2]);
        float ov = sigm(t1[3]);
        cb = fv * cb + iv * gv;
        float h = ov * tanh_acc(cb);
        sh[wr1 + b1 * V2S] = h;
        if (HAS2) sh[wr2 + b1 * V2S] = h;
    }
}

__global__ void __launch_bounds__(NTHREADS, 1)
lstm3_pipe_kernel(const float* __restrict__ x,
                  const float* __restrict__ Wih1, const float* __restrict__ Whh1,
                  const float* __restrict__ bih1, const float* __restrict__ bhh1,
                  const float* __restrict__ Wih2, const float* __restrict__ Whh2,
                  const float* __restrict__ bih2, const float* __restrict__ bhh2,
                  const float* __restrict__ Wih3, const float* __restrict__ Whh3,
                  const float* __restrict__ bih3, const float* __restrict__ bhh3,
                  const float* __restrict__ fcW, const float* __restrict__ fcb,
                  float* __restrict__ out) {
    extern __shared__ float sh[];
    const int tid = threadIdx.x;
    const int bid = blockIdx.x;
    const int lane = tid & 31;

    int b0, cnt;
    if (bid < 136) { b0 = bid * 7;               cnt = 7; }
    else           { b0 = 952 + (bid - 136) * 6; cnt = 6; }

    // zero v buffers
    for (int i = V1_OFF + tid; i < SH_FLOATS; i += NTHREADS) sh[i] = 0.0f;

    // stage weights: [kq][row][k&3], kq-stride WSTR
    for (int idx = tid; idx < 200 * 56; idx += NTHREADS) {
        int g = idx / 56, k = idx - g * 56;
        float v;
        if (k < IN_DIM)       v = Wih1[g * IN_DIM + k];
        else if (k == IN_DIM) v = 0.0f;
        else                  v = Whh1[g * HID + (k - 6)];
        sh[W1_OFF + (k >> 2) * WSTR + g * 4 + (k & 3)] = v;
    }
    for (int idx = tid; idx < 200 * 100; idx += NTHREADS) {
        int g = idx / 100, k = idx - g * 100;
        float v = (k < HID) ? Wih2[g * HID + k] : Whh2[g * HID + (k - HID)];
        sh[W2_OFF + (k >> 2) * WSTR + g * 4 + (k & 3)] = v;
    }
    for (int idx = tid; idx < 200 * 100; idx += NTHREADS) {
        int g = idx / 100, k = idx - g * 100;
        float v = (k < HID) ? Wih3[g * HID + k] : Whh3[g * HID + (k - HID)];
        sh[W3_OFF + (k >> 2) * WSTR + g * 4 + (k & 3)] = v;
    }
    // x(t=0) into v1 buf0
    if (tid < NB * IN_DIM) {
        int b = tid / IN_DIM, d = tid - b * IN_DIM;
        if (b < cnt)
            sh[V1_OFF + b * V1S + d] = x[(size_t)(b0 + b) * T_STEPS * IN_DIM + d];
    }

    // ---- group assignment ----
    const bool isL1 = (tid < 100);
    const bool isL2 = (tid >= 100 && tid < 300);
    const bool isL3 = (tid >= 300 && tid < 500);
    const bool isSp = (tid >= 500);

    int j = 0, ks = 0;
    if (isL1)      { j = tid >> 1;          ks = tid & 1; }
    else if (isL2) { int i2 = tid - 100; j = i2 >> 2; ks = i2 & 3; }
    else if (isL3) { int i3 = tid - 300; j = i3 >> 2; ks = i3 & 3; }

    const unsigned pmask = 0x3u << (lane & ~1);   // L1 pair mask
    const unsigned qmask = 0xFu << (lane & ~3);   // L2/L3 quad mask

    float bz[4] = {0.f, 0.f, 0.f, 0.f};
    if (isL1) {
#pragma unroll
        for (int g = 0; g < 4; g++)
            bz[g] = bih1[g * HID + j] + bhh1[g * HID + j];
    } else if (isL2) {
#pragma unroll
        for (int g = 0; g < 4; g++)
            bz[g] = bih2[g * HID + j] + bhh2[g * HID + j];
    } else if (isL3) {
#pragma unroll
        for (int g = 0; g < 4; g++)
            bz[g] = bih3[g * HID + j] + bhh3[g * HID + j];
    }

    float c1[4] = {0.f, 0.f, 0.f, 0.f};   // L1: 4 (ks=0) or 3 (ks=1) batches
    float ca = 0.f, cb = 0.f;             // L2/L3 cell states

    const int sp_i = tid - 500;           // 12 spares x 3 slots = 36 >= 35
    __syncthreads();

    for (int ph = 0; ph < T_STEPS + 2; ph++) {
        const int p = ph & 1, q = p ^ 1;

        if (isL1) {
            if (ph < T_STEPS)
                layer1_phase(sh, p, q, j, ks, pmask, bz, c1);
        } else if (isL2) {
            if (ph >= 1 && ph <= T_STEPS)
                layer_hid_phase<true>(sh, sh + W2_OFF,
                                      sh + V2_OFF + p * V2B,
                                      j, ks, qmask, bz, ca, cb,
                                      V2_OFF + q * V2B + HID + j,
                                      V3_OFF + q * V2B + j);
        } else if (isL3) {
            if (ph >= 2)
                layer_hid_phase<false>(sh, sh + W3_OFF,
                                       sh + V3_OFF + p * V2B,
                                       j, ks, qmask, bz, ca, cb,
                                       V3_OFF + q * V2B + HID + j, 0);
        } else if (isSp) {
            if (ph + 1 < T_STEPS) {
#pragma unroll
                for (int r = 0; r < 3; r++) {
                    int s0 = sp_i + 12 * r;
                    if (s0 < NB * IN_DIM) {
                        int bb = s0 / IN_DIM, dd = s0 - bb * IN_DIM;
                        if (bb < cnt)
                            sh[V1_OFF + q * V1B + bb * V1S + dd] =
                                x[(size_t)(b0 + bb) * T_STEPS * IN_DIM
                                  + (ph + 1) * IN_DIM + dd];
                    }
                }
            }
        }
        __syncthreads();
    }

    // FC: final h3 in v3 buf0
    if (tid < cnt) {
        float a = fcb[0];
#pragma unroll
        for (int jj = 0; jj < HID; jj++)
            a += fcW[jj] * sh[V3_OFF + tid * V2S + HID + jj];
        out[b0 + tid] = a;
    }
}

extern "C" void kernel_launch(void* const* d_in, const int* in_sizes, int n_in,
                              void* d_out, int out_size) {
    const float* x    = (const float*)d_in[0];
    const float* Wih1 = (const float*)d_in[1];
    const float* Whh1 = (const float*)d_in[2];
    const float* bih1 = (const float*)d_in[3];
    const float* bhh1 = (const float*)d_in[4];
    const float* Wih2 = (const float*)d_in[5];
    const float* Whh2 = (const float*)d_in[6];
    const float* bih2 = (const float*)d_in[7];
    const float* bhh2 = (const float*)d_in[8];
    const float* Wih3 = (const float*)d_in[9];
    const float* Whh3 = (const float*)d_in[10];
    const float* bih3 = (const float*)d_in[11];
    const float* bhh3 = (const float*)d_in[12];
    const float* fcW  = (const float*)d_in[13];
    const float* fcb  = (const float*)d_in[14];

    size_t shbytes = (size_t)SH_FLOATS * sizeof(float);
    cudaFuncSetAttribute(lstm3_pipe_kernel,
                         cudaFuncAttributeMaxDynamicSharedMemorySize,
                         (int)shbytes);
    lstm3_pipe_kernel<<<GRID, NTHREADS, shbytes>>>(
        x, Wih1, Whh1, bih1, bhh1, Wih2, Whh2, bih2, bhh2,
        Wih3, Whh3, bih3, bhh3, fcW, fcb, (float*)d_out);
}